// round 10
// baseline (speedup 1.0000x reference)
#include <cuda_runtime.h>
#include <cuda_bf16.h>
#include <cuda_fp16.h>
#include <cstdint>

#define NN      50000
#define EE      800000
#define INDIM   256
#define TD      16
#define HID     256
#define NUMT    50
#define AUG     (INDIM + TD)

// ---------------- scratch ----------------
__device__ int   g_cnt[NN];
__device__ int   g_off[NN + 1];
__device__ int   g_cur[NN];
__device__ int   g_bsum[128];
__device__ int   g_bpre[128];
__device__ int   g_csr[EE];
__device__ __half g_xh[(size_t)NN * INDIM];       // fp16 x
__device__ __half g_wh[(size_t)512 * INDIM];      // fp16 [W1l ; W1r] (first 256 cols)
__device__ __nv_bfloat16 g_zh[(size_t)NN * HID];  // bf16 z
__device__ float g_r[(size_t)NN * HID];           // fp32 r
__device__ float g_teL[NUMT * HID];
__device__ float g_teR[NUMT * HID];
__device__ float g_sl[NN];
__device__ float g_sr[NN];

// ---------------- CSR build ----------------
__global__ void k_zero(int n) {
    int i = blockIdx.x * blockDim.x + threadIdx.x;
    if (i < n) g_cnt[i] = 0;
}

__global__ void k_count(const int* __restrict__ edge, int E) {
    int e = blockIdx.x * blockDim.x + threadIdx.x;
    if (e < E) atomicAdd(&g_cnt[edge[E + e]], 1);
}

#define SCAN_B 512
__global__ __launch_bounds__(SCAN_B) void k_scan1(int n) {
    __shared__ int ws[16];
    const int tid = threadIdx.x, lane = tid & 31, w = tid >> 5;
    const int idx = blockIdx.x * SCAN_B + tid;
    int v = (idx < n) ? g_cnt[idx] : 0;
    int sv = v;
    #pragma unroll
    for (int o = 1; o < 32; o <<= 1) {
        int t = __shfl_up_sync(0xffffffffu, sv, o);
        if (lane >= o) sv += t;
    }
    if (lane == 31) ws[w] = sv;
    __syncthreads();
    if (w == 0) {
        int t = (lane < 16) ? ws[lane] : 0;
        #pragma unroll
        for (int o = 1; o < 16; o <<= 1) {
            int u = __shfl_up_sync(0xffffffffu, t, o);
            if (lane >= o) t += u;
        }
        if (lane < 16) ws[lane] = t;
    }
    __syncthreads();
    int excl = (w ? ws[w - 1] : 0) + sv - v;
    if (idx < n) g_off[idx] = excl;
    if (tid == 0) g_bsum[blockIdx.x] = ws[15];
}

__global__ void k_scan2(int nb, int n) {
    __shared__ int wsum[5];
    const int tid = threadIdx.x, lane = tid & 31, w = tid >> 5;
    int v = (tid < nb) ? g_bsum[tid] : 0;
    int sv = v;
    #pragma unroll
    for (int o = 1; o < 32; o <<= 1) {
        int t = __shfl_up_sync(0xffffffffu, sv, o);
        if (lane >= o) sv += t;
    }
    if (lane == 31) wsum[w] = sv;
    __syncthreads();
    if (tid == 0) {
        int a = 0;
        #pragma unroll
        for (int i = 0; i < 4; i++) { int t = wsum[i]; wsum[i] = a; a += t; }
        wsum[4] = a;
    }
    __syncthreads();
    int excl = wsum[w] + sv - v;
    if (tid < nb) g_bpre[tid] = excl;
    if (tid == 0) g_off[n] = wsum[4];
}

__global__ __launch_bounds__(SCAN_B) void k_scan3(int n) {
    int idx = blockIdx.x * SCAN_B + threadIdx.x;
    if (idx < n) {
        int o = g_off[idx] + g_bpre[blockIdx.x];
        g_off[idx] = o;
        g_cur[idx] = o;
    }
}

__global__ void k_fill(const int* __restrict__ edge, int E) {
    int e = blockIdx.x * blockDim.x + threadIdx.x;
    if (e < E) {
        int s = edge[e];
        int d = edge[E + e];
        int p = atomicAdd(&g_cur[d], 1);
        g_csr[p] = s;
    }
}

// ---------------- time tables + fp16 conversions ----------------
__global__ void k_teproj(const float* __restrict__ te,
                         const float* __restrict__ W1l,
                         const float* __restrict__ W1r,
                         const float* __restrict__ b1) {
    int t = blockIdx.x;
    int h = threadIdx.x;
    float sl = 0.f, sr = 0.f;
    #pragma unroll
    for (int d = 0; d < TD; ++d) {
        float tv = te[t * TD + d];
        sl += tv * W1l[h * AUG + INDIM + d];
        sr += tv * W1r[h * AUG + INDIM + d];
    }
    g_teL[t * HID + h] = sl;
    g_teR[t * HID + h] = sr + b1[h];
}

__global__ __launch_bounds__(256) void k_cvtx(const float* __restrict__ x, int n4) {
    int i = blockIdx.x * blockDim.x + threadIdx.x;
    if (i >= n4) return;
    float4 v = reinterpret_cast<const float4*>(x)[i];
    __half2 h0 = __floats2half2_rn(v.x, v.y);
    __half2 h1 = __floats2half2_rn(v.z, v.w);
    uint2 o;
    o.x = *reinterpret_cast<uint32_t*>(&h0);
    o.y = *reinterpret_cast<uint32_t*>(&h1);
    reinterpret_cast<uint2*>(g_xh)[i] = o;
}

__global__ void k_cvtw(const float* __restrict__ W1l, const float* __restrict__ W1r) {
    int row = blockIdx.x;        // 0..511
    int c = threadIdx.x;         // 0..255
    const float* src = (row < 256) ? (W1l + (size_t)row * AUG) : (W1r + (size_t)(row - 256) * AUG);
    g_wh[(size_t)row * INDIM + c] = __float2half_rn(src[c]);
}

// ---------------- fp16 tensor-core GEMM with ldmatrix ----------------
#define BM 128
#define BN 128
#define BK 32
#define LDH 40                   // halves per row (80 B) -> conflict-free ldmatrix
#define HSZ (BM * LDH)           // halves per tile per stage
#define GEMM_SMEM (4 * HSZ * 2)  // A 2 stages + B 2 stages, fp16

__device__ __forceinline__ void cpa16(void* dst, const void* src, bool valid) {
    uint32_t d = (uint32_t)__cvta_generic_to_shared(dst);
    int sz = valid ? 16 : 0;
    asm volatile("cp.async.cg.shared.global [%0], [%1], 16, %2;\n"
                 :: "r"(d), "l"(src), "r"(sz));
}

__device__ __forceinline__ void mma_f16(float4& d, const uint32_t a[4], const uint32_t b[2]) {
    asm volatile(
        "mma.sync.aligned.m16n8k16.row.col.f32.f16.f16.f32 "
        "{%0,%1,%2,%3}, {%4,%5,%6,%7}, {%8,%9}, {%0,%1,%2,%3};\n"
        : "+f"(d.x), "+f"(d.y), "+f"(d.z), "+f"(d.w)
        : "r"(a[0]), "r"(a[1]), "r"(a[2]), "r"(a[3]), "r"(b[0]), "r"(b[1]));
}

__device__ __forceinline__ void ldsm_x4(uint32_t& r0, uint32_t& r1, uint32_t& r2, uint32_t& r3,
                                        uint32_t addr) {
    asm volatile("ldmatrix.sync.aligned.m8n8.x4.shared.b16 {%0,%1,%2,%3}, [%4];"
                 : "=r"(r0), "=r"(r1), "=r"(r2), "=r"(r3) : "r"(addr));
}

// A: fp16 from g_xh, B: fp16 from g_wh — each 128 rows x 4 chunks of 8 halves
__device__ __forceinline__ void load_tile(__half* As, __half* Bs,
                                          int m0, int cbase, int M, int kb, int tid) {
    #pragma unroll
    for (int i = 0; i < 2; i++) {
        int idx = tid + 256 * i;
        int row = idx >> 2, c8 = (idx & 3) * 8;
        int m = m0 + row;
        bool va = m < M;
        cpa16(As + row * LDH + c8, g_xh + (size_t)(va ? m : 0) * INDIM + kb + c8, va);
        cpa16(Bs + row * LDH + c8, g_wh + (size_t)(cbase + row) * INDIM + kb + c8, true);
    }
}

__global__ __launch_bounds__(256) void k_gemm(const int* __restrict__ ts, int M) {
    extern __shared__ __half smh[];
    __half* As  = smh;                 // [2][BM][LDH]
    __half* Bsm = smh + 2 * HSZ;       // [2][BN][LDH]

    const int tid = threadIdx.x;
    const int n0 = blockIdx.x * BN;
    const int m0 = blockIdx.y * BM;
    const bool isZ = (n0 < 256);
    const int cbase = n0;
    const int cloc = isZ ? n0 : (n0 - 256);

    const int warp = tid >> 5, lane = tid & 31;
    const int wm = warp >> 2, wn = warp & 3;
    const int g = lane >> 2, tig = lane & 3;

    // ldmatrix lane-address components (in halves)
    const int a_row = (lane & 15);            // + wm*64 + mt*16
    const int a_col = (lane >> 4) * 8;        // + kk*16
    const int b_row = ((lane >> 4) * 8) + (lane & 7);  // + wn*32 + p*16
    const int b_col = ((lane >> 3) & 1) * 8;  // + kk*16

    const uint32_t sA = (uint32_t)__cvta_generic_to_shared(As);
    const uint32_t sB = (uint32_t)__cvta_generic_to_shared(Bsm);

    float4 acc[4][4];
    #pragma unroll
    for (int i = 0; i < 4; i++)
        #pragma unroll
        for (int j = 0; j < 4; j++) acc[i][j] = make_float4(0.f, 0.f, 0.f, 0.f);

    load_tile(As, Bsm, m0, cbase, M, 0, tid);
    asm volatile("cp.async.commit_group;\n");
    load_tile(As + HSZ, Bsm + HSZ, m0, cbase, M, BK, tid);
    asm volatile("cp.async.commit_group;\n");
    asm volatile("cp.async.wait_group 1;\n");
    __syncthreads();

    #pragma unroll 1
    for (int ks = 0; ks < INDIM / BK; ks++) {
        const int buf = ks & 1;
        const uint32_t Ab = sA + (uint32_t)(buf * HSZ) * 2;
        const uint32_t Bb = sB + (uint32_t)(buf * HSZ) * 2;

        #pragma unroll
        for (int kk = 0; kk < 2; kk++) {           // 2 x K=16
            uint32_t af[4][4], bf[4][2];
            #pragma unroll
            for (int mt = 0; mt < 4; mt++) {
                uint32_t addr = Ab + (uint32_t)((wm * 64 + mt * 16 + a_row) * LDH
                                                + kk * 16 + a_col) * 2;
                ldsm_x4(af[mt][0], af[mt][1], af[mt][2], af[mt][3], addr);
            }
            #pragma unroll
            for (int p = 0; p < 2; p++) {
                uint32_t addr = Bb + (uint32_t)((wn * 32 + p * 16 + b_row) * LDH
                                                + kk * 16 + b_col) * 2;
                ldsm_x4(bf[2 * p][0], bf[2 * p][1], bf[2 * p + 1][0], bf[2 * p + 1][1], addr);
            }
            #pragma unroll
            for (int mt = 0; mt < 4; mt++)
                #pragma unroll
                for (int nt = 0; nt < 4; nt++)
                    mma_f16(acc[mt][nt], af[mt], bf[nt]);
        }
        __syncthreads();
        if (ks + 2 < INDIM / BK) {
            load_tile(As + buf * HSZ, Bsm + buf * HSZ, m0, cbase, M, (ks + 2) * BK, tid);
            asm volatile("cp.async.commit_group;\n");
            asm volatile("cp.async.wait_group 1;\n");
        } else {
            asm volatile("cp.async.wait_group 0;\n");
        }
        __syncthreads();
    }

    // epilogue: add time tables; z -> bf16, r -> fp32
    const float* tabB = isZ ? g_teL : g_teR;
    #pragma unroll
    for (int mt = 0; mt < 4; mt++) {
        int mtp = m0 + wm * 64 + mt * 16 + g;
        int mbt = mtp + 8;
        int t0 = (mtp < M) ? ts[mtp] : 0;
        int t1 = (mbt < M) ? ts[mbt] : 0;
        const float* tb0 = tabB + t0 * HID;
        const float* tb1 = tabB + t1 * HID;
        #pragma unroll
        for (int nt = 0; nt < 4; nt++) {
            int c = cloc + wn * 32 + nt * 8 + tig * 2;
            if (isZ) {
                if (mtp < M) {
                    __nv_bfloat162 v = __floats2bfloat162_rn(acc[mt][nt].x + tb0[c],
                                                             acc[mt][nt].y + tb0[c + 1]);
                    *reinterpret_cast<__nv_bfloat162*>(g_zh + (size_t)mtp * HID + c) = v;
                }
                if (mbt < M) {
                    __nv_bfloat162 v = __floats2bfloat162_rn(acc[mt][nt].z + tb1[c],
                                                             acc[mt][nt].w + tb1[c + 1]);
                    *reinterpret_cast<__nv_bfloat162*>(g_zh + (size_t)mbt * HID + c) = v;
                }
            } else {
                if (mtp < M) {
                    float2 v; v.x = acc[mt][nt].x + tb0[c]; v.y = acc[mt][nt].y + tb0[c + 1];
                    *reinterpret_cast<float2*>(g_r + (size_t)mtp * HID + c) = v;
                }
                if (mbt < M) {
                    float2 v; v.x = acc[mt][nt].z + tb1[c]; v.y = acc[mt][nt].w + tb1[c + 1];
                    *reinterpret_cast<float2*>(g_r + (size_t)mbt * HID + c) = v;
                }
            }
        }
    }
}

// ---------------- layer-1 aggregation (bf16 z, node per warp) ----------------
__global__ __launch_bounds__(256) void k_agg(const float* __restrict__ Whl,
                                             const float* __restrict__ Whr,
                                             int n) {
    const int warp = threadIdx.x >> 5, lane = threadIdx.x & 31;
    const int node = blockIdx.x * 8 + warp;
    if (node >= n) return;

    const int beg = g_off[node], end = g_off[node + 1];
    const int deg = end - beg;
    const uint4* __restrict__ Z = reinterpret_cast<const uint4*>(g_zh);

    float a[8];
    #pragma unroll
    for (int i = 0; i < 8; i++) a[i] = 0.f;

    int e = beg;
    for (; e + 7 < end; e += 8) {
        uint4 v[8];
        #pragma unroll
        for (int q = 0; q < 8; q++)
            v[q] = Z[(size_t)g_csr[e + q] * 32 + lane];
        #pragma unroll
        for (int q = 0; q < 8; q++) {
            float2 p0 = __bfloat1622float2(*reinterpret_cast<__nv_bfloat162*>(&v[q].x));
            float2 p1 = __bfloat1622float2(*reinterpret_cast<__nv_bfloat162*>(&v[q].y));
            float2 p2 = __bfloat1622float2(*reinterpret_cast<__nv_bfloat162*>(&v[q].z));
            float2 p3 = __bfloat1622float2(*reinterpret_cast<__nv_bfloat162*>(&v[q].w));
            a[0] += p0.x; a[1] += p0.y; a[2] += p1.x; a[3] += p1.y;
            a[4] += p2.x; a[5] += p2.y; a[6] += p3.x; a[7] += p3.y;
        }
    }
    for (; e < end; e++) {
        uint4 v = Z[(size_t)g_csr[e] * 32 + lane];
        float2 p0 = __bfloat1622float2(*reinterpret_cast<__nv_bfloat162*>(&v.x));
        float2 p1 = __bfloat1622float2(*reinterpret_cast<__nv_bfloat162*>(&v.y));
        float2 p2 = __bfloat1622float2(*reinterpret_cast<__nv_bfloat162*>(&v.z));
        float2 p3 = __bfloat1622float2(*reinterpret_cast<__nv_bfloat162*>(&v.w));
        a[0] += p0.x; a[1] += p0.y; a[2] += p1.x; a[3] += p1.y;
        a[4] += p2.x; a[5] += p2.y; a[6] += p3.x; a[7] += p3.y;
    }

    const float inv = 1.0f / (float)max(deg, 1);
    const float4* R4 = reinterpret_cast<const float4*>(g_r) + (size_t)node * 64;
    float4 r0 = R4[2 * lane], r1 = R4[2 * lane + 1];
    float h[8];
    h[0] = fmaxf(fmaf(a[0], inv, r0.x), 0.f);
    h[1] = fmaxf(fmaf(a[1], inv, r0.y), 0.f);
    h[2] = fmaxf(fmaf(a[2], inv, r0.z), 0.f);
    h[3] = fmaxf(fmaf(a[3], inv, r0.w), 0.f);
    h[4] = fmaxf(fmaf(a[4], inv, r1.x), 0.f);
    h[5] = fmaxf(fmaf(a[5], inv, r1.y), 0.f);
    h[6] = fmaxf(fmaf(a[6], inv, r1.z), 0.f);
    h[7] = fmaxf(fmaf(a[7], inv, r1.w), 0.f);

    const float4* WL = reinterpret_cast<const float4*>(Whl);
    const float4* WR = reinterpret_cast<const float4*>(Whr);
    float4 wl0 = __ldg(&WL[2 * lane]), wl1 = __ldg(&WL[2 * lane + 1]);
    float4 wr0 = __ldg(&WR[2 * lane]), wr1 = __ldg(&WR[2 * lane + 1]);

    float sl = h[0] * wl0.x + h[1] * wl0.y + h[2] * wl0.z + h[3] * wl0.w
             + h[4] * wl1.x + h[5] * wl1.y + h[6] * wl1.z + h[7] * wl1.w;
    float sr = h[0] * wr0.x + h[1] * wr0.y + h[2] * wr0.z + h[3] * wr0.w
             + h[4] * wr1.x + h[5] * wr1.y + h[6] * wr1.z + h[7] * wr1.w;

    #pragma unroll
    for (int o = 16; o > 0; o >>= 1) {
        sl += __shfl_xor_sync(0xffffffffu, sl, o);
        sr += __shfl_xor_sync(0xffffffffu, sr, o);
    }
    if (lane == 0) { g_sl[node] = sl; g_sr[node] = sr; }
}

// ---------------- layer-2 scalar aggregation ----------------
__global__ void k_out(const float* __restrict__ bh, float* __restrict__ out, int n) {
    int node = blockIdx.x * blockDim.x + threadIdx.x;
    if (node >= n) return;
    int beg = g_off[node], end = g_off[node + 1];
    float s = 0.f;
    int e = beg;
    for (; e + 7 < end; e += 8) {
        float s0 = g_sl[g_csr[e]];
        float s1 = g_sl[g_csr[e + 1]];
        float s2 = g_sl[g_csr[e + 2]];
        float s3 = g_sl[g_csr[e + 3]];
        float s4 = g_sl[g_csr[e + 4]];
        float s5 = g_sl[g_csr[e + 5]];
        float s6 = g_sl[g_csr[e + 6]];
        float s7 = g_sl[g_csr[e + 7]];
        s += ((s0 + s1) + (s2 + s3)) + ((s4 + s5) + (s6 + s7));
    }
    for (; e < end; ++e) s += g_sl[g_csr[e]];
    out[node] = s / (float)max(end - beg, 1) + bh[0] + g_sr[node];
}

// ---------------- launch ----------------
// Submission order keeps k_gemm 4th (ncu captures submission #4).
extern "C" void kernel_launch(void* const* d_in, const int* in_sizes, int n_in,
                              void* d_out, int out_size) {
    const float* x    = (const float*)d_in[0];
    const int*   edge = (const int*)  d_in[1];
    const int*   ts   = (const int*)  d_in[2];
    const float* te   = (const float*)d_in[3];
    const float* W1l  = (const float*)d_in[4];
    const float* b1   = (const float*)d_in[5];
    const float* W1r  = (const float*)d_in[6];
    const float* Whl  = (const float*)d_in[7];
    const float* bh   = (const float*)d_in[8];
    const float* Whr  = (const float*)d_in[9];
    float* out = (float*)d_out;

    const int N = in_sizes[0] / INDIM;
    const int E = in_sizes[1] / 2;
    const int NB = (N + SCAN_B - 1) / SCAN_B;

    static cudaStream_t s_side = nullptr;
    static cudaEvent_t ev_fork = nullptr, ev_csr = nullptr;
    static int inited = 0;
    if (!inited) {
        cudaFuncSetAttribute(k_gemm, cudaFuncAttributeMaxDynamicSharedMemorySize, GEMM_SMEM);
        cudaStreamCreateWithFlags(&s_side, cudaStreamNonBlocking);
        cudaEventCreateWithFlags(&ev_fork, cudaEventDisableTiming);
        cudaEventCreateWithFlags(&ev_csr, cudaEventDisableTiming);
        inited = 1;
    }

    dim3 gg(512 / BN, (N + BM - 1) / BM);
    const int n4 = N * INDIM / 4;

    // main: cvtw(1), teproj(2), cvtx(3), gemm(4)
    cudaEventRecord(ev_fork, 0);
    k_cvtw  <<<512, 256>>>(W1l, W1r);
    k_teproj<<<NUMT, HID>>>(te, W1l, W1r, b1);
    k_cvtx  <<<(n4 + 255) / 256, 256>>>(x, n4);
    k_gemm  <<<gg, 256, GEMM_SMEM>>>(ts, N);

    // side: CSR build, concurrent with main chain
    cudaStreamWaitEvent(s_side, ev_fork, 0);
    k_zero  <<<(N + 255) / 256, 256, 0, s_side>>>(N);
    k_count <<<(E + 255) / 256, 256, 0, s_side>>>(edge, E);
    k_scan1 <<<NB, SCAN_B, 0, s_side>>>(N);
    k_scan2 <<<1, 128, 0, s_side>>>(NB, N);
    k_scan3 <<<NB, SCAN_B, 0, s_side>>>(N);
    k_fill  <<<(E + 255) / 256, 256, 0, s_side>>>(edge, E);
    cudaEventRecord(ev_csr, s_side);

    // join, then aggregate
    cudaStreamWaitEvent(0, ev_csr, 0);
    k_agg   <<<(N + 7) / 8, 256>>>(Whl, Whr, N);
    k_out   <<<(N + 255) / 256, 256>>>(bh, out, N);
}

// round 11
// speedup vs baseline: 1.0577x; 1.0577x over previous
#include <cuda_runtime.h>
#include <cuda_bf16.h>
#include <cuda_fp16.h>
#include <cstdint>

#define NN      50000
#define EE      800000
#define INDIM   256
#define TD      16
#define HID     256
#define NUMT    50
#define AUG     (INDIM + TD)

// ---------------- scratch ----------------
__device__ int   g_cnt[NN];
__device__ int   g_off[NN + 1];
__device__ int   g_cur[NN];
__device__ int   g_bsum[128];
__device__ int   g_bpre[128];
__device__ int   g_csr[EE];
__device__ __half g_xh[(size_t)NN * INDIM];       // fp16 x
__device__ __half g_wh[(size_t)512 * INDIM];      // fp16 [W1l ; W1r] (first 256 cols)
__device__ __nv_bfloat16 g_zh[(size_t)NN * HID];  // bf16 z
__device__ float g_r[(size_t)NN * HID];           // fp32 r
__device__ float g_teL[NUMT * HID];
__device__ float g_teR[NUMT * HID];
__device__ float g_sl[NN];
__device__ float g_sr[NN];

// ---------------- CSR build ----------------
__global__ void k_zero(int n) {
    int i = blockIdx.x * blockDim.x + threadIdx.x;
    if (i < n) g_cnt[i] = 0;
}

__global__ void k_count(const int* __restrict__ edge, int E) {
    int e = blockIdx.x * blockDim.x + threadIdx.x;
    if (e < E) atomicAdd(&g_cnt[edge[E + e]], 1);
}

#define SCAN_B 512
__global__ __launch_bounds__(SCAN_B) void k_scan1(int n) {
    __shared__ int ws[16];
    const int tid = threadIdx.x, lane = tid & 31, w = tid >> 5;
    const int idx = blockIdx.x * SCAN_B + tid;
    int v = (idx < n) ? g_cnt[idx] : 0;
    int sv = v;
    #pragma unroll
    for (int o = 1; o < 32; o <<= 1) {
        int t = __shfl_up_sync(0xffffffffu, sv, o);
        if (lane >= o) sv += t;
    }
    if (lane == 31) ws[w] = sv;
    __syncthreads();
    if (w == 0) {
        int t = (lane < 16) ? ws[lane] : 0;
        #pragma unroll
        for (int o = 1; o < 16; o <<= 1) {
            int u = __shfl_up_sync(0xffffffffu, t, o);
            if (lane >= o) t += u;
        }
        if (lane < 16) ws[lane] = t;
    }
    __syncthreads();
    int excl = (w ? ws[w - 1] : 0) + sv - v;
    if (idx < n) g_off[idx] = excl;
    if (tid == 0) g_bsum[blockIdx.x] = ws[15];
}

__global__ void k_scan2(int nb, int n) {
    __shared__ int wsum[5];
    const int tid = threadIdx.x, lane = tid & 31, w = tid >> 5;
    int v = (tid < nb) ? g_bsum[tid] : 0;
    int sv = v;
    #pragma unroll
    for (int o = 1; o < 32; o <<= 1) {
        int t = __shfl_up_sync(0xffffffffu, sv, o);
        if (lane >= o) sv += t;
    }
    if (lane == 31) wsum[w] = sv;
    __syncthreads();
    if (tid == 0) {
        int a = 0;
        #pragma unroll
        for (int i = 0; i < 4; i++) { int t = wsum[i]; wsum[i] = a; a += t; }
        wsum[4] = a;
    }
    __syncthreads();
    int excl = wsum[w] + sv - v;
    if (tid < nb) g_bpre[tid] = excl;
    if (tid == 0) g_off[n] = wsum[4];
}

__global__ __launch_bounds__(SCAN_B) void k_scan3(int n) {
    int idx = blockIdx.x * SCAN_B + threadIdx.x;
    if (idx < n) {
        int o = g_off[idx] + g_bpre[blockIdx.x];
        g_off[idx] = o;
        g_cur[idx] = o;
    }
}

__global__ void k_fill(const int* __restrict__ edge, int E) {
    int e = blockIdx.x * blockDim.x + threadIdx.x;
    if (e < E) {
        int s = edge[e];
        int d = edge[E + e];
        int p = atomicAdd(&g_cur[d], 1);
        g_csr[p] = s;
    }
}

// ---------------- time tables + fp16 conversions ----------------
__global__ void k_teproj(const float* __restrict__ te,
                         const float* __restrict__ W1l,
                         const float* __restrict__ W1r,
                         const float* __restrict__ b1) {
    int t = blockIdx.x;
    int h = threadIdx.x;
    float sl = 0.f, sr = 0.f;
    #pragma unroll
    for (int d = 0; d < TD; ++d) {
        float tv = te[t * TD + d];
        sl += tv * W1l[h * AUG + INDIM + d];
        sr += tv * W1r[h * AUG + INDIM + d];
    }
    g_teL[t * HID + h] = sl;
    g_teR[t * HID + h] = sr + b1[h];
}

__global__ __launch_bounds__(256) void k_cvtx(const float* __restrict__ x, int n4) {
    int i = blockIdx.x * blockDim.x + threadIdx.x;
    if (i >= n4) return;
    float4 v = reinterpret_cast<const float4*>(x)[i];
    __half2 h0 = __floats2half2_rn(v.x, v.y);
    __half2 h1 = __floats2half2_rn(v.z, v.w);
    uint2 o;
    o.x = *reinterpret_cast<uint32_t*>(&h0);
    o.y = *reinterpret_cast<uint32_t*>(&h1);
    reinterpret_cast<uint2*>(g_xh)[i] = o;
}

__global__ void k_cvtw(const float* __restrict__ W1l, const float* __restrict__ W1r) {
    int row = blockIdx.x;        // 0..511
    int c = threadIdx.x;         // 0..255
    const float* src = (row < 256) ? (W1l + (size_t)row * AUG) : (W1r + (size_t)(row - 256) * AUG);
    g_wh[(size_t)row * INDIM + c] = __float2half_rn(src[c]);
}

// ---------------- fp16 tensor-core GEMM: 512 thr, 3-stage, 1 sync/iter ----------
#define BM 128
#define BN 128
#define BK 32
#define NSTAGE 3
#define LDH 40                   // halves per row (80 B) -> conflict-free ldmatrix
#define HSZ (BM * LDH)           // halves per tile per stage
#define GEMM_SMEM (2 * NSTAGE * HSZ * 2)   // A + B, 3 stages, fp16 = 61440 B

__device__ __forceinline__ void cpa16(void* dst, const void* src, bool valid) {
    uint32_t d = (uint32_t)__cvta_generic_to_shared(dst);
    int sz = valid ? 16 : 0;
    asm volatile("cp.async.cg.shared.global [%0], [%1], 16, %2;\n"
                 :: "r"(d), "l"(src), "r"(sz));
}

__device__ __forceinline__ void mma_f16(float4& d, const uint32_t a[4], const uint32_t b[2]) {
    asm volatile(
        "mma.sync.aligned.m16n8k16.row.col.f32.f16.f16.f32 "
        "{%0,%1,%2,%3}, {%4,%5,%6,%7}, {%8,%9}, {%0,%1,%2,%3};\n"
        : "+f"(d.x), "+f"(d.y), "+f"(d.z), "+f"(d.w)
        : "r"(a[0]), "r"(a[1]), "r"(a[2]), "r"(a[3]), "r"(b[0]), "r"(b[1]));
}

__device__ __forceinline__ void ldsm_x4(uint32_t& r0, uint32_t& r1, uint32_t& r2, uint32_t& r3,
                                        uint32_t addr) {
    asm volatile("ldmatrix.sync.aligned.m8n8.x4.shared.b16 {%0,%1,%2,%3}, [%4];"
                 : "=r"(r0), "=r"(r1), "=r"(r2), "=r"(r3) : "r"(addr));
}

// 512 threads: A 128 rows x 4 chunks = 512 cp16 -> 1/thread; B same
__device__ __forceinline__ void load_tile(__half* As, __half* Bs,
                                          int m0, int cbase, int M, int kb, int tid) {
    int row = tid >> 2, c8 = (tid & 3) * 8;
    int m = m0 + row;
    bool va = m < M;
    cpa16(As + row * LDH + c8, g_xh + (size_t)(va ? m : 0) * INDIM + kb + c8, va);
    cpa16(Bs + row * LDH + c8, g_wh + (size_t)(cbase + row) * INDIM + kb + c8, true);
}

__global__ __launch_bounds__(512, 2) void k_gemm(const int* __restrict__ ts, int M) {
    extern __shared__ __half smh[];
    __half* As  = smh;                       // [NSTAGE][BM][LDH]
    __half* Bsm = smh + NSTAGE * HSZ;        // [NSTAGE][BN][LDH]

    const int tid = threadIdx.x;
    const int n0 = blockIdx.x * BN;
    const int m0 = blockIdx.y * BM;
    const bool isZ = (n0 < 256);
    const int cbase = n0;
    const int cloc = isZ ? n0 : (n0 - 256);

    const int warp = tid >> 5, lane = tid & 31;
    const int wm = warp >> 2, wn = warp & 3;   // 4x4 warp grid, 32x32 warp tile
    const int g = lane >> 2, tig = lane & 3;

    const int a_row = (lane & 15);
    const int a_col = (lane >> 4) * 8;
    const int b_row = ((lane >> 4) * 8) + (lane & 7);
    const int b_col = ((lane >> 3) & 1) * 8;

    const uint32_t sA = (uint32_t)__cvta_generic_to_shared(As);
    const uint32_t sB = (uint32_t)__cvta_generic_to_shared(Bsm);

    float4 acc[2][4];
    #pragma unroll
    for (int i = 0; i < 2; i++)
        #pragma unroll
        for (int j = 0; j < 4; j++) acc[i][j] = make_float4(0.f, 0.f, 0.f, 0.f);

    load_tile(As, Bsm, m0, cbase, M, 0, tid);
    asm volatile("cp.async.commit_group;\n");
    load_tile(As + HSZ, Bsm + HSZ, m0, cbase, M, BK, tid);
    asm volatile("cp.async.commit_group;\n");

    #pragma unroll 1
    for (int ks = 0; ks < INDIM / BK; ks++) {
        if (ks < INDIM / BK - 1) asm volatile("cp.async.wait_group 1;\n");
        else                     asm volatile("cp.async.wait_group 0;\n");
        __syncthreads();

        if (ks + 2 < INDIM / BK) {
            int st = (ks + 2) % NSTAGE;
            load_tile(As + st * HSZ, Bsm + st * HSZ, m0, cbase, M, (ks + 2) * BK, tid);
            asm volatile("cp.async.commit_group;\n");
        }

        const int cs = ks % NSTAGE;
        const uint32_t Ab = sA + (uint32_t)(cs * HSZ) * 2;
        const uint32_t Bb = sB + (uint32_t)(cs * HSZ) * 2;

        #pragma unroll
        for (int kk = 0; kk < 2; kk++) {
            uint32_t af[2][4], bf[4][2];
            #pragma unroll
            for (int mt = 0; mt < 2; mt++) {
                uint32_t addr = Ab + (uint32_t)((wm * 32 + mt * 16 + a_row) * LDH
                                                + kk * 16 + a_col) * 2;
                ldsm_x4(af[mt][0], af[mt][1], af[mt][2], af[mt][3], addr);
            }
            #pragma unroll
            for (int p = 0; p < 2; p++) {
                uint32_t addr = Bb + (uint32_t)((wn * 32 + p * 16 + b_row) * LDH
                                                + kk * 16 + b_col) * 2;
                ldsm_x4(bf[2 * p][0], bf[2 * p][1], bf[2 * p + 1][0], bf[2 * p + 1][1], addr);
            }
            #pragma unroll
            for (int mt = 0; mt < 2; mt++)
                #pragma unroll
                for (int nt = 0; nt < 4; nt++)
                    mma_f16(acc[mt][nt], af[mt], bf[nt]);
        }
    }

    // epilogue: add time tables; z -> bf16, r -> fp32
    const float* tabB = isZ ? g_teL : g_teR;
    #pragma unroll
    for (int mt = 0; mt < 2; mt++) {
        int mtp = m0 + wm * 32 + mt * 16 + g;
        int mbt = mtp + 8;
        int t0 = (mtp < M) ? ts[mtp] : 0;
        int t1 = (mbt < M) ? ts[mbt] : 0;
        const float* tb0 = tabB + t0 * HID;
        const float* tb1 = tabB + t1 * HID;
        #pragma unroll
        for (int nt = 0; nt < 4; nt++) {
            int c = cloc + wn * 32 + nt * 8 + tig * 2;
            if (isZ) {
                if (mtp < M) {
                    __nv_bfloat162 v = __floats2bfloat162_rn(acc[mt][nt].x + tb0[c],
                                                             acc[mt][nt].y + tb0[c + 1]);
                    *reinterpret_cast<__nv_bfloat162*>(g_zh + (size_t)mtp * HID + c) = v;
                }
                if (mbt < M) {
                    __nv_bfloat162 v = __floats2bfloat162_rn(acc[mt][nt].z + tb1[c],
                                                             acc[mt][nt].w + tb1[c + 1]);
                    *reinterpret_cast<__nv_bfloat162*>(g_zh + (size_t)mbt * HID + c) = v;
                }
            } else {
                if (mtp < M) {
                    float2 v; v.x = acc[mt][nt].x + tb0[c]; v.y = acc[mt][nt].y + tb0[c + 1];
                    *reinterpret_cast<float2*>(g_r + (size_t)mtp * HID + c) = v;
                }
                if (mbt < M) {
                    float2 v; v.x = acc[mt][nt].z + tb1[c]; v.y = acc[mt][nt].w + tb1[c + 1];
                    *reinterpret_cast<float2*>(g_r + (size_t)mbt * HID + c) = v;
                }
            }
        }
    }
}

// ---------------- layer-1 aggregation (bf16 z, node per warp) ----------------
__global__ __launch_bounds__(256) void k_agg(const float* __restrict__ Whl,
                                             const float* __restrict__ Whr,
                                             int n) {
    const int warp = threadIdx.x >> 5, lane = threadIdx.x & 31;
    const int node = blockIdx.x * 8 + warp;
    if (node >= n) return;

    const int beg = g_off[node], end = g_off[node + 1];
    const int deg = end - beg;
    const uint4* __restrict__ Z = reinterpret_cast<const uint4*>(g_zh);

    float a[8];
    #pragma unroll
    for (int i = 0; i < 8; i++) a[i] = 0.f;

    int e = beg;
    for (; e + 7 < end; e += 8) {
        uint4 v[8];
        #pragma unroll
        for (int q = 0; q < 8; q++)
            v[q] = Z[(size_t)g_csr[e + q] * 32 + lane];
        #pragma unroll
        for (int q = 0; q < 8; q++) {
            float2 p0 = __bfloat1622float2(*reinterpret_cast<__nv_bfloat162*>(&v[q].x));
            float2 p1 = __bfloat1622float2(*reinterpret_cast<__nv_bfloat162*>(&v[q].y));
            float2 p2 = __bfloat1622float2(*reinterpret_cast<__nv_bfloat162*>(&v[q].z));
            float2 p3 = __bfloat1622float2(*reinterpret_cast<__nv_bfloat162*>(&v[q].w));
            a[0] += p0.x; a[1] += p0.y; a[2] += p1.x; a[3] += p1.y;
            a[4] += p2.x; a[5] += p2.y; a[6] += p3.x; a[7] += p3.y;
        }
    }
    for (; e < end; e++) {
        uint4 v = Z[(size_t)g_csr[e] * 32 + lane];
        float2 p0 = __bfloat1622float2(*reinterpret_cast<__nv_bfloat162*>(&v.x));
        float2 p1 = __bfloat1622float2(*reinterpret_cast<__nv_bfloat162*>(&v.y));
        float2 p2 = __bfloat1622float2(*reinterpret_cast<__nv_bfloat162*>(&v.z));
        float2 p3 = __bfloat1622float2(*reinterpret_cast<__nv_bfloat162*>(&v.w));
        a[0] += p0.x; a[1] += p0.y; a[2] += p1.x; a[3] += p1.y;
        a[4] += p2.x; a[5] += p2.y; a[6] += p3.x; a[7] += p3.y;
    }

    const float inv = 1.0f / (float)max(deg, 1);
    const float4* R4 = reinterpret_cast<const float4*>(g_r) + (size_t)node * 64;
    float4 r0 = R4[2 * lane], r1 = R4[2 * lane + 1];
    float h[8];
    h[0] = fmaxf(fmaf(a[0], inv, r0.x), 0.f);
    h[1] = fmaxf(fmaf(a[1], inv, r0.y), 0.f);
    h[2] = fmaxf(fmaf(a[2], inv, r0.z), 0.f);
    h[3] = fmaxf(fmaf(a[3], inv, r0.w), 0.f);
    h[4] = fmaxf(fmaf(a[4], inv, r1.x), 0.f);
    h[5] = fmaxf(fmaf(a[5], inv, r1.y), 0.f);
    h[6] = fmaxf(fmaf(a[6], inv, r1.z), 0.f);
    h[7] = fmaxf(fmaf(a[7], inv, r1.w), 0.f);

    const float4* WL = reinterpret_cast<const float4*>(Whl);
    const float4* WR = reinterpret_cast<const float4*>(Whr);
    float4 wl0 = __ldg(&WL[2 * lane]), wl1 = __ldg(&WL[2 * lane + 1]);
    float4 wr0 = __ldg(&WR[2 * lane]), wr1 = __ldg(&WR[2 * lane + 1]);

    float sl = h[0] * wl0.x + h[1] * wl0.y + h[2] * wl0.z + h[3] * wl0.w
             + h[4] * wl1.x + h[5] * wl1.y + h[6] * wl1.z + h[7] * wl1.w;
    float sr = h[0] * wr0.x + h[1] * wr0.y + h[2] * wr0.z + h[3] * wr0.w
             + h[4] * wr1.x + h[5] * wr1.y + h[6] * wr1.z + h[7] * wr1.w;

    #pragma unroll
    for (int o = 16; o > 0; o >>= 1) {
        sl += __shfl_xor_sync(0xffffffffu, sl, o);
        sr += __shfl_xor_sync(0xffffffffu, sr, o);
    }
    if (lane == 0) { g_sl[node] = sl; g_sr[node] = sr; }
}

// ---------------- layer-2 scalar aggregation ----------------
__global__ void k_out(const float* __restrict__ bh, float* __restrict__ out, int n) {
    int node = blockIdx.x * blockDim.x + threadIdx.x;
    if (node >= n) return;
    int beg = g_off[node], end = g_off[node + 1];
    float s = 0.f;
    int e = beg;
    for (; e + 7 < end; e += 8) {
        float s0 = g_sl[g_csr[e]];
        float s1 = g_sl[g_csr[e + 1]];
        float s2 = g_sl[g_csr[e + 2]];
        float s3 = g_sl[g_csr[e + 3]];
        float s4 = g_sl[g_csr[e + 4]];
        float s5 = g_sl[g_csr[e + 5]];
        float s6 = g_sl[g_csr[e + 6]];
        float s7 = g_sl[g_csr[e + 7]];
        s += ((s0 + s1) + (s2 + s3)) + ((s4 + s5) + (s6 + s7));
    }
    for (; e < end; ++e) s += g_sl[g_csr[e]];
    out[node] = s / (float)max(end - beg, 1) + bh[0] + g_sr[node];
}

// ---------------- launch ----------------
// Submission order keeps k_gemm 4th (ncu captures submission #4).
extern "C" void kernel_launch(void* const* d_in, const int* in_sizes, int n_in,
                              void* d_out, int out_size) {
    const float* x    = (const float*)d_in[0];
    const int*   edge = (const int*)  d_in[1];
    const int*   ts   = (const int*)  d_in[2];
    const float* te   = (const float*)d_in[3];
    const float* W1l  = (const float*)d_in[4];
    const float* b1   = (const float*)d_in[5];
    const float* W1r  = (const float*)d_in[6];
    const float* Whl  = (const float*)d_in[7];
    const float* bh   = (const float*)d_in[8];
    const float* Whr  = (const float*)d_in[9];
    float* out = (float*)d_out;

    const int N = in_sizes[0] / INDIM;
    const int E = in_sizes[1] / 2;
    const int NB = (N + SCAN_B - 1) / SCAN_B;

    static cudaStream_t s_side = nullptr;
    static cudaEvent_t ev_fork = nullptr, ev_csr = nullptr;
    static int inited = 0;
    if (!inited) {
        cudaFuncSetAttribute(k_gemm, cudaFuncAttributeMaxDynamicSharedMemorySize, GEMM_SMEM);
        cudaStreamCreateWithFlags(&s_side, cudaStreamNonBlocking);
        cudaEventCreateWithFlags(&ev_fork, cudaEventDisableTiming);
        cudaEventCreateWithFlags(&ev_csr, cudaEventDisableTiming);
        inited = 1;
    }

    dim3 gg(512 / BN, (N + BM - 1) / BM);
    const int n4 = N * INDIM / 4;

    // main: cvtw(1), teproj(2), cvtx(3), gemm(4)
    cudaEventRecord(ev_fork, 0);
    k_cvtw  <<<512, 256>>>(W1l, W1r);
    k_teproj<<<NUMT, HID>>>(te, W1l, W1r, b1);
    k_cvtx  <<<(n4 + 255) / 256, 256>>>(x, n4);
    k_gemm  <<<gg, 512, GEMM_SMEM>>>(ts, N);

    // side: CSR build, concurrent with main chain
    cudaStreamWaitEvent(s_side, ev_fork, 0);
    k_zero  <<<(N + 255) / 256, 256, 0, s_side>>>(N);
    k_count <<<(E + 255) / 256, 256, 0, s_side>>>(edge, E);
    k_scan1 <<<NB, SCAN_B, 0, s_side>>>(N);
    k_scan2 <<<1, 128, 0, s_side>>>(NB, N);
    k_scan3 <<<NB, SCAN_B, 0, s_side>>>(N);
    k_fill  <<<(E + 255) / 256, 256, 0, s_side>>>(edge, E);
    cudaEventRecord(ev_csr, s_side);

    // join, then aggregate
    cudaStreamWaitEvent(0, ev_csr, 0);
    k_agg   <<<(N + 7) / 8, 256>>>(Whl, Whr, N);
    k_out   <<<(N + 255) / 256, 256>>>(bh, out, N);
}